// round 1
// baseline (speedup 1.0000x reference)
#include <cuda_runtime.h>

// Problem constants
#define MDIM 16384   // B*S = 4*4096 rows
#define KDIM 1024    // d_model
#define NDIM 1024    // n_heads*d_k = d_model
#define BM 128
#define BN 128
#define BK 16

// Scratch (device globals: no allocation allowed in kernel_launch)
__device__ float g_q[(size_t)MDIM * NDIM];
__device__ float g_k[(size_t)MDIM * NDIM];
__device__ float g_v[(size_t)MDIM * NDIM];
__device__ float g_x[(size_t)MDIM * NDIM];

// ---------- packed f32x2 helpers (FFMA2: 2 FMAs per instruction) ----------
__device__ __forceinline__ unsigned long long pk2(float lo, float hi) {
    unsigned long long r;
    unsigned a = __float_as_uint(lo), b = __float_as_uint(hi);
    asm("mov.b64 %0, {%1, %2};" : "=l"(r) : "r"(a), "r"(b));
    return r;
}
__device__ __forceinline__ void upk2(unsigned long long v, float& lo, float& hi) {
    unsigned a, b;
    asm("mov.b64 {%0, %1}, %2;" : "=r"(a), "=r"(b) : "l"(v));
    lo = __uint_as_float(a);
    hi = __uint_as_float(b);
}
__device__ __forceinline__ void ffma2(unsigned long long& c, unsigned long long a,
                                      unsigned long long b) {
    asm("fma.rn.f32x2 %0, %1, %2, %3;" : "=l"(c) : "l"(a), "l"(b), "l"(c));
}

// ---------- GEMM: C[m,n] = sum_k A[m,k]*W[n,k] + bias[n] ----------
// A: [MDIM, KDIM] row-major; W: [NDIM, KDIM] row-major (i.e. we apply W^T).
// 128x128 CTA tile, 8x8 per-thread microtile, BK=16, double-buffered SMEM.
#define STORE_TILE(dst)                                                         \
    do {                                                                        \
        As[dst][lk + 0][lr] = ra0.x;  As[dst][lk + 1][lr] = ra0.y;              \
        As[dst][lk + 2][lr] = ra0.z;  As[dst][lk + 3][lr] = ra0.w;              \
        As[dst][lk + 0][lr + 64] = ra1.x;  As[dst][lk + 1][lr + 64] = ra1.y;    \
        As[dst][lk + 2][lr + 64] = ra1.z;  As[dst][lk + 3][lr + 64] = ra1.w;    \
        Bs[dst][lk + 0][lr] = rb0.x;  Bs[dst][lk + 1][lr] = rb0.y;              \
        Bs[dst][lk + 2][lr] = rb0.z;  Bs[dst][lk + 3][lr] = rb0.w;              \
        Bs[dst][lk + 0][lr + 64] = rb1.x;  Bs[dst][lk + 1][lr + 64] = rb1.y;    \
        Bs[dst][lk + 2][lr + 64] = rb1.z;  Bs[dst][lk + 3][lr + 64] = rb1.w;    \
    } while (0)

__device__ __forceinline__ void gemm_body(const float* __restrict__ A,
                                          const float* __restrict__ W,
                                          const float* __restrict__ bias,
                                          float* __restrict__ C) {
    __shared__ float As[2][BK][BM + 4];   // +4 pad: 2-way instead of 4-way store conflicts
    __shared__ float Bs[2][BK][BN + 4];

    const int t  = threadIdx.x;
    const int m0 = blockIdx.y * BM;
    const int n0 = blockIdx.x * BN;
    const int lr  = t >> 2;          // 0..63 (tile row for loads)
    const int lk  = (t & 3) << 2;    // 0,4,8,12 (k offset for loads)
    const int tm8 = (t >> 4) << 3;   // microtile row base
    const int tn8 = (t & 15) << 3;   // microtile col base

    const float* Ap0 = A + (size_t)(m0 + lr) * KDIM + lk;
    const float* Ap1 = Ap0 + (size_t)64 * KDIM;
    const float* Wp0 = W + (size_t)(n0 + lr) * KDIM + lk;
    const float* Wp1 = Wp0 + (size_t)64 * KDIM;

    unsigned long long c[8][4];      // c[i][j] = cols (2j, 2j+1) of row i (packed f32x2)
#pragma unroll
    for (int i = 0; i < 8; i++)
#pragma unroll
        for (int j = 0; j < 4; j++) c[i][j] = 0ULL;

    // Prologue: load tile 0 into regs, stage to smem buf 0
    float4 ra0 = *(const float4*)(Ap0);
    float4 ra1 = *(const float4*)(Ap1);
    float4 rb0 = *(const float4*)(Wp0);
    float4 rb1 = *(const float4*)(Wp1);
    STORE_TILE(0);
    __syncthreads();

    const int NT = KDIM / BK;  // 64 k-tiles
#pragma unroll 1
    for (int tt = 0; tt < NT; tt++) {
        const int cur = tt & 1;
        if (tt + 1 < NT) {
            const int ko = (tt + 1) * BK;
            ra0 = *(const float4*)(Ap0 + ko);
            ra1 = *(const float4*)(Ap1 + ko);
            rb0 = *(const float4*)(Wp0 + ko);
            rb1 = *(const float4*)(Wp1 + ko);
        }
#pragma unroll
        for (int kk = 0; kk < BK; kk++) {
            float4 a0 = *(const float4*)&As[cur][kk][tm8];
            float4 a1 = *(const float4*)&As[cur][kk][tm8 + 4];
            float4 b0 = *(const float4*)&Bs[cur][kk][tn8];
            float4 b1 = *(const float4*)&Bs[cur][kk][tn8 + 4];
            unsigned long long bp0 = pk2(b0.x, b0.y);
            unsigned long long bp1 = pk2(b0.z, b0.w);
            unsigned long long bp2 = pk2(b1.x, b1.y);
            unsigned long long bp3 = pk2(b1.z, b1.w);
            float av[8] = {a0.x, a0.y, a0.z, a0.w, a1.x, a1.y, a1.z, a1.w};
#pragma unroll
            for (int i = 0; i < 8; i++) {
                unsigned long long aa = pk2(av[i], av[i]);
                ffma2(c[i][0], aa, bp0);
                ffma2(c[i][1], aa, bp1);
                ffma2(c[i][2], aa, bp2);
                ffma2(c[i][3], aa, bp3);
            }
        }
        if (tt + 1 < NT) STORE_TILE(cur ^ 1);
        __syncthreads();
    }

    // Epilogue: add bias, write C (float2 stores; L2 merges 32B sectors)
    float bc[8];
#pragma unroll
    for (int j = 0; j < 8; j++) bc[j] = bias[n0 + tn8 + j];
#pragma unroll
    for (int i = 0; i < 8; i++) {
        float* crow = C + (size_t)(m0 + tm8 + i) * NDIM + n0 + tn8;
#pragma unroll
        for (int j = 0; j < 4; j++) {
            float lo, hi;
            upk2(c[i][j], lo, hi);
            float2 o;
            o.x = lo + bc[2 * j];
            o.y = hi + bc[2 * j + 1];
            *(float2*)(crow + 2 * j) = o;
        }
    }
}

__global__ __launch_bounds__(256, 2)
void qkv_gemm_kernel(const float* __restrict__ Q, const float* __restrict__ K,
                     const float* __restrict__ V,
                     const float* __restrict__ Wq, const float* __restrict__ bq,
                     const float* __restrict__ Wk, const float* __restrict__ bk,
                     const float* __restrict__ Wv, const float* __restrict__ bv) {
    const int z = blockIdx.z;
    const float* A = (z == 0) ? Q : (z == 1) ? K : V;
    const float* W = (z == 0) ? Wq : (z == 1) ? Wk : Wv;
    const float* b = (z == 0) ? bq : (z == 1) ? bk : bv;
    float* C       = (z == 0) ? g_q : (z == 1) ? g_k : g_v;
    gemm_body(A, W, b, C);
}

__global__ __launch_bounds__(256, 2)
void out_gemm_kernel(const float* __restrict__ Wo, const float* __restrict__ bo,
                     float* __restrict__ out) {
    gemm_body(g_x, Wo, bo, out);
}

// ---------- Per-token head-attention (the reference's transpose-bug semantics) ----------
// For each token (b,s): q,k,v in R^{16x64}; scores[h,g] = q[h]·k[g]/8; softmax over g;
// out[h,:] = sum_g attn[h,g] v[g,:]. Written directly in the scrambled layout:
// X[b, h*256 + s/16, (s%16)*64 + d].
__global__ __launch_bounds__(256)
void attn_kernel() {
    const int token = blockIdx.x;            // b*S + s
    const int b = token >> 12;
    const int s = token & 4095;
    __shared__ float qs[16 * 64];
    __shared__ float ks[16 * 68];            // padded rows: avoid 16-way bank conflict
    __shared__ float vs[16 * 64];
    __shared__ float at[16][16];

    const int t = threadIdx.x;
    const size_t base = (size_t)token * 1024;
    {
        float4 qv = ((const float4*)(g_q + base))[t];
        float4 kv = ((const float4*)(g_k + base))[t];
        float4 vv = ((const float4*)(g_v + base))[t];
        ((float4*)qs)[t] = qv;
        ((float4*)vs)[t] = vv;
        const int gg = t >> 4, dd = (t & 15) << 2;
        *(float4*)(ks + gg * 68 + dd) = kv;
    }
    __syncthreads();

    const int h = t >> 4, g = t & 15;
    const float* qr = qs + h * 64;
    const float* kr = ks + g * 68;
    float acc = 0.f;
#pragma unroll
    for (int d = 0; d < 64; d += 4) {
        float4 qa = *(const float4*)(qr + d);
        float4 ka = *(const float4*)(kr + d);
        acc += qa.x * ka.x + qa.y * ka.y + qa.z * ka.z + qa.w * ka.w;
    }
    float sc = acc * 0.125f;                 // 1/sqrt(64)
    float mx = sc;
#pragma unroll
    for (int d = 8; d; d >>= 1) mx = fmaxf(mx, __shfl_xor_sync(0xffffffffu, mx, d));
    float p = __expf(sc - mx);
    float sm = p;
#pragma unroll
    for (int d = 8; d; d >>= 1) sm += __shfl_xor_sync(0xffffffffu, sm, d);
    at[h][g] = p / sm;
    __syncthreads();

    const int h2 = t >> 4, db = (t & 15) << 2;
    float4 o = make_float4(0.f, 0.f, 0.f, 0.f);
#pragma unroll
    for (int gg = 0; gg < 16; gg++) {
        const float w = at[h2][gg];
        const float* vr = vs + gg * 64 + db;
        o.x += w * vr[0];
        o.y += w * vr[1];
        o.z += w * vr[2];
        o.w += w * vr[3];
    }
    const size_t row = (size_t)b * 4096 + (size_t)h2 * 256 + (s >> 4);
    *(float4*)(g_x + row * 1024 + (s & 15) * 64 + db) = o;
}

// ---------- launch ----------
extern "C" void kernel_launch(void* const* d_in, const int* in_sizes, int n_in,
                              void* d_out, int out_size) {
    (void)in_sizes; (void)n_in; (void)out_size;
    const float* query = (const float*)d_in[0];
    const float* key   = (const float*)d_in[1];
    const float* value = (const float*)d_in[2];
    const float* Wq = (const float*)d_in[3];
    const float* bq = (const float*)d_in[4];
    const float* Wk = (const float*)d_in[5];
    const float* bk = (const float*)d_in[6];
    const float* Wv = (const float*)d_in[7];
    const float* bv = (const float*)d_in[8];
    const float* Wo = (const float*)d_in[9];
    const float* bo = (const float*)d_in[10];
    float* out = (float*)d_out;

    dim3 grid_qkv(NDIM / BN, MDIM / BM, 3);
    qkv_gemm_kernel<<<grid_qkv, 256>>>(query, key, value, Wq, bq, Wk, bk, Wv, bv);
    attn_kernel<<<MDIM, 256>>>();
    out_gemm_kernel<<<dim3(NDIM / BN, MDIM / BM, 1), 256>>>(Wo, bo, out);
}

// round 3
// speedup vs baseline: 1.9879x; 1.9879x over previous
#include <cuda_runtime.h>
#include <cuda_bf16.h>
#include <cstdint>

// ---------------- problem constants ----------------
#define MDIM 16384          // B*S
#define KD   1024           // d_model = heads*dk
#define NELEM ((size_t)MDIM * KD)
#define WELEM ((size_t)KD * KD)

// GEMM tiling
#define TM 128
#define TN 128
#define BK 32               // k elems per chunk
#define NCH (KD / BK)       // 32 chunks
#define PITCH 40            // smem row pitch in bf16 elems (80B -> conflict-free ldmatrix)
#define TEN_BYTES (128 * PITCH * 2)        // 10240 bytes per tensor tile
#define STAGE_BYTES (4 * TEN_BYTES)        // Ah, Al, Bh, Bl
#define STAGES 3
#define SMEM_DYN (STAGES * STAGE_BYTES)    // 122880

// ---------------- device scratch ----------------
__device__ float g_q[NELEM];
__device__ float g_k[NELEM];
__device__ float g_v[NELEM];
__device__ float g_x[NELEM];
__device__ __nv_bfloat16 g_iqh[NELEM], g_iql[NELEM];
__device__ __nv_bfloat16 g_ikh[NELEM], g_ikl[NELEM];
__device__ __nv_bfloat16 g_ivh[NELEM], g_ivl[NELEM];
__device__ __nv_bfloat16 g_xh[NELEM],  g_xl[NELEM];
__device__ __nv_bfloat16 g_wh[4][WELEM], g_wl[4][WELEM];

// ---------------- PTX helpers ----------------
__device__ __forceinline__ uint32_t smem_u32(const void* p) {
    uint32_t a;
    asm("{ .reg .u64 t; cvta.to.shared.u64 t, %1; cvt.u32.u64 %0, t; }" : "=r"(a) : "l"(p));
    return a;
}
__device__ __forceinline__ void cp16(uint32_t dst, const void* src) {
    asm volatile("cp.async.cg.shared.global [%0], [%1], 16;" :: "r"(dst), "l"(src));
}
__device__ __forceinline__ void cp_commit() { asm volatile("cp.async.commit_group;"); }
__device__ __forceinline__ void ldm_x4(uint32_t r[4], uint32_t addr) {
    asm volatile("ldmatrix.sync.aligned.m8n8.x4.shared.b16 {%0,%1,%2,%3}, [%4];"
                 : "=r"(r[0]), "=r"(r[1]), "=r"(r[2]), "=r"(r[3]) : "r"(addr));
}
__device__ __forceinline__ void mma16816(float c[4], const uint32_t a[4],
                                         uint32_t b0, uint32_t b1) {
    asm volatile(
        "mma.sync.aligned.m16n8k16.row.col.f32.bf16.bf16.f32 "
        "{%0,%1,%2,%3}, {%4,%5,%6,%7}, {%8,%9}, {%0,%1,%2,%3};"
        : "+f"(c[0]), "+f"(c[1]), "+f"(c[2]), "+f"(c[3])
        : "r"(a[0]), "r"(a[1]), "r"(a[2]), "r"(a[3]), "r"(b0), "r"(b1));
}

// ---------------- GEMM: C[16384,1024] = A*W^T + bias (bf16x3 split) ----------------
// A hi/lo: [MDIM, KD] bf16 row-major.  W hi/lo: [KD(out), KD(in)] bf16 row-major.
__device__ __forceinline__ void mma_gemm_body(
    const __nv_bfloat16* __restrict__ Ah, const __nv_bfloat16* __restrict__ Al,
    const __nv_bfloat16* __restrict__ Wh, const __nv_bfloat16* __restrict__ Wl,
    const float* __restrict__ bias, float* __restrict__ C)
{
    extern __shared__ char dynsm[];
    const uint32_t sb = smem_u32(dynsm);

    const int t    = threadIdx.x;
    const int lane = t & 31;
    const int wid  = t >> 5;
    const int wm   = (wid >> 2) * 64;    // warp m offset (0 / 64)
    const int wn   = (wid & 3) * 32;     // warp n offset (0/32/64/96)
    const int m0   = blockIdx.y * TM;
    const int n0   = blockIdx.x * TN;

    const char* pAh = (const char*)Ah;
    const char* pAl = (const char*)Al;
    const char* pWh = (const char*)Wh;
    const char* pWl = (const char*)Wl;

    float acc[4][4][4];
#pragma unroll
    for (int i = 0; i < 4; i++)
#pragma unroll
        for (int j = 0; j < 4; j++)
#pragma unroll
            for (int r = 0; r < 4; r++) acc[i][j][r] = 0.f;

    // per-thread load slots: 512 16B-chunks per tensor per chunk-step
    const int j0 = t, j1 = t + 256;
    const int r0 = j0 >> 2, q0 = j0 & 3;
    const int r1 = j1 >> 2, q1 = j1 & 3;
    const uint32_t d0 = (uint32_t)(r0 * 80 + q0 * 16);
    const uint32_t d1 = (uint32_t)(r1 * 80 + q1 * 16);
    const size_t ga0 = (size_t)(m0 + r0) * 2048 + q0 * 16;
    const size_t ga1 = (size_t)(m0 + r1) * 2048 + q1 * 16;
    const size_t gb0 = (size_t)(n0 + r0) * 2048 + q0 * 16;
    const size_t gb1 = (size_t)(n0 + r1) * 2048 + q1 * 16;

    auto load_chunk = [&](int c, int buf) {
        const uint32_t s = sb + (uint32_t)buf * STAGE_BYTES;
        const size_t kb = (size_t)c * 64;
        cp16(s + d0,                 pAh + ga0 + kb);
        cp16(s + d1,                 pAh + ga1 + kb);
        cp16(s + TEN_BYTES + d0,     pAl + ga0 + kb);
        cp16(s + TEN_BYTES + d1,     pAl + ga1 + kb);
        cp16(s + 2 * TEN_BYTES + d0, pWh + gb0 + kb);
        cp16(s + 2 * TEN_BYTES + d1, pWh + gb1 + kb);
        cp16(s + 3 * TEN_BYTES + d0, pWl + gb0 + kb);
        cp16(s + 3 * TEN_BYTES + d1, pWl + gb1 + kb);
    };

    load_chunk(0, 0); cp_commit();
    load_chunk(1, 1); cp_commit();
    load_chunk(2, 2); cp_commit();

    // per-lane ldmatrix address pieces (byte offsets within a tensor tile)
    // A tiles: rows m + (lane&15), col byte ks*32 + (lane>>4)*16
    const uint32_t a_row = (uint32_t)(wm + (lane & 15));
    const uint32_t a_cb  = (uint32_t)((lane >> 4) * 16);
    // B tiles: rows n + (lane&7) + ((lane>>4)<<3), col byte ks*32 + ((lane>>3)&1)*16
    const uint32_t b_row = (uint32_t)(wn + (lane & 7) + ((lane >> 4) << 3));
    const uint32_t b_cb  = (uint32_t)(((lane >> 3) & 1) * 16);

#pragma unroll 1
    for (int c = 0; c < NCH; c++) {
        asm volatile("cp.async.wait_group %0;" :: "n"(STAGES - 1));
        __syncthreads();

        const uint32_t s  = sb + (uint32_t)(c % STAGES) * STAGE_BYTES;
        const uint32_t sAh = s;
        const uint32_t sAl = s + TEN_BYTES;
        const uint32_t sBh = s + 2 * TEN_BYTES;
        const uint32_t sBl = s + 3 * TEN_BYTES;

#pragma unroll
        for (int ks = 0; ks < 2; ks++) {
            const uint32_t kb = (uint32_t)(ks * 32);
            uint32_t ah[4][4], al[4][4], bh[2][4], bl[2][4];
#pragma unroll
            for (int mt = 0; mt < 4; mt++) {
                const uint32_t ao = (a_row + mt * 16) * 80 + kb + a_cb;
                ldm_x4(ah[mt], sAh + ao);
                ldm_x4(al[mt], sAl + ao);
            }
#pragma unroll
            for (int nt = 0; nt < 2; nt++) {
                const uint32_t bo = (b_row + nt * 16) * 80 + kb + b_cb;
                ldm_x4(bh[nt], sBh + bo);
                ldm_x4(bl[nt], sBl + bo);
            }
#pragma unroll
            for (int mt = 0; mt < 4; mt++) {
#pragma unroll
                for (int j = 0; j < 4; j++) {
                    const int p = j >> 1, e = (j & 1) * 2;
                    mma16816(acc[mt][j], ah[mt], bh[p][e], bh[p][e + 1]);
                    mma16816(acc[mt][j], ah[mt], bl[p][e], bl[p][e + 1]);
                    mma16816(acc[mt][j], al[mt], bh[p][e], bh[p][e + 1]);
                }
            }
        }
        __syncthreads();
        if (c + STAGES < NCH) load_chunk(c + STAGES, c % STAGES);
        cp_commit();
    }

    // epilogue: bias + store
    const int tr = lane >> 2;            // 0..7
    const int tc = (lane & 3) * 2;       // 0,2,4,6
#pragma unroll
    for (int mt = 0; mt < 4; mt++) {
        const int gr = m0 + wm + mt * 16 + tr;
        float* row0 = C + (size_t)gr * KD + n0 + wn;
        float* row1 = row0 + 8 * KD;
#pragma unroll
        for (int j = 0; j < 4; j++) {
            const int gc = wn + j * 8 + tc;
            float2 bb = *(const float2*)(bias + n0 + gc);
            float2 o0, o1;
            o0.x = acc[mt][j][0] + bb.x;  o0.y = acc[mt][j][1] + bb.y;
            o1.x = acc[mt][j][2] + bb.x;  o1.y = acc[mt][j][3] + bb.y;
            *(float2*)(row0 + j * 8 + tc) = o0;
            *(float2*)(row1 + j * 8 + tc) = o1;
        }
    }
}

__global__ __launch_bounds__(256, 1)
void qkv_mma_kernel(const float* __restrict__ bq, const float* __restrict__ bk,
                    const float* __restrict__ bv) {
    const int z = blockIdx.z;
    const __nv_bfloat16* Ah = (z == 0) ? g_iqh : (z == 1) ? g_ikh : g_ivh;
    const __nv_bfloat16* Al = (z == 0) ? g_iql : (z == 1) ? g_ikl : g_ivl;
    const float* bias = (z == 0) ? bq : (z == 1) ? bk : bv;
    float* C = (z == 0) ? g_q : (z == 1) ? g_k : g_v;
    mma_gemm_body(Ah, Al, g_wh[z], g_wl[z], bias, C);
}

__global__ __launch_bounds__(256, 1)
void out_mma_kernel(const float* __restrict__ bo, float* __restrict__ out) {
    mma_gemm_body(g_xh, g_xl, g_wh[3], g_wl[3], bo, out);
}

// ---------------- fp32 -> bf16 hi/lo split ----------------
__device__ __forceinline__ void split4(const float4 v, __nv_bfloat16* hi, __nv_bfloat16* lo,
                                       size_t i4) {
    __nv_bfloat16 hx = __float2bfloat16_rn(v.x);
    __nv_bfloat16 hy = __float2bfloat16_rn(v.y);
    __nv_bfloat16 hz = __float2bfloat16_rn(v.z);
    __nv_bfloat16 hw = __float2bfloat16_rn(v.w);
    __nv_bfloat16 lx = __float2bfloat16_rn(v.x - __bfloat162float(hx));
    __nv_bfloat16 ly = __float2bfloat16_rn(v.y - __bfloat162float(hy));
    __nv_bfloat16 lz = __float2bfloat16_rn(v.z - __bfloat162float(hz));
    __nv_bfloat16 lw = __float2bfloat16_rn(v.w - __bfloat162float(hw));
    ((__nv_bfloat162*)hi)[2 * i4]     = __halves2bfloat162(hx, hy);
    ((__nv_bfloat162*)hi)[2 * i4 + 1] = __halves2bfloat162(hz, hw);
    ((__nv_bfloat162*)lo)[2 * i4]     = __halves2bfloat162(lx, ly);
    ((__nv_bfloat162*)lo)[2 * i4 + 1] = __halves2bfloat162(lz, lw);
}

__global__ __launch_bounds__(256)
void split_act_kernel(const float* __restrict__ q, const float* __restrict__ k,
                      const float* __restrict__ v) {
    const int z = blockIdx.y;
    const float* src = (z == 0) ? q : (z == 1) ? k : v;
    __nv_bfloat16* hi = (z == 0) ? g_iqh : (z == 1) ? g_ikh : g_ivh;
    __nv_bfloat16* lo = (z == 0) ? g_iql : (z == 1) ? g_ikl : g_ivl;
    const size_t n4 = NELEM / 4;
    const size_t stride = (size_t)gridDim.x * blockDim.x;
    for (size_t i = (size_t)blockIdx.x * blockDim.x + threadIdx.x; i < n4; i += stride)
        split4(((const float4*)src)[i], hi, lo, i);
}

__global__ __launch_bounds__(256)
void split_w_kernel(const float* __restrict__ wq, const float* __restrict__ wk,
                    const float* __restrict__ wv, const float* __restrict__ wo) {
    const int z = blockIdx.y;
    const float* src = (z == 0) ? wq : (z == 1) ? wk : (z == 2) ? wv : wo;
    __nv_bfloat16* hi = g_wh[z];
    __nv_bfloat16* lo = g_wl[z];
    const size_t n4 = WELEM / 4;
    const size_t stride = (size_t)gridDim.x * blockDim.x;
    for (size_t i = (size_t)blockIdx.x * blockDim.x + threadIdx.x; i < n4; i += stride)
        split4(((const float4*)src)[i], hi, lo, i);
}

__global__ __launch_bounds__(256)
void split_x_kernel() {
    const size_t n4 = NELEM / 4;
    const size_t stride = (size_t)gridDim.x * blockDim.x;
    for (size_t i = (size_t)blockIdx.x * blockDim.x + threadIdx.x; i < n4; i += stride)
        split4(((const float4*)g_x)[i], g_xh, g_xl, i);
}

// ---------------- per-token head attention (reference's transposed semantics) ----------------
__global__ __launch_bounds__(256)
void attn_kernel() {
    const int token = blockIdx.x;
    const int b = token >> 12;
    const int s = token & 4095;
    __shared__ float qs[16 * 64];
    __shared__ float ks[16 * 68];
    __shared__ float vs[16 * 64];
    __shared__ float at[16][16];

    const int t = threadIdx.x;
    const size_t base = (size_t)token * 1024;
    {
        float4 qv = ((const float4*)(g_q + base))[t];
        float4 kv = ((const float4*)(g_k + base))[t];
        float4 vv = ((const float4*)(g_v + base))[t];
        ((float4*)qs)[t] = qv;
        ((float4*)vs)[t] = vv;
        const int gg = t >> 4, dd = (t & 15) << 2;
        *(float4*)(ks + gg * 68 + dd) = kv;
    }
    __syncthreads();

    const int h = t >> 4, g = t & 15;
    const float* qr = qs + h * 64;
    const float* kr = ks + g * 68;
    float acc = 0.f;
#pragma unroll
    for (int d = 0; d < 64; d += 4) {
        float4 qa = *(const float4*)(qr + d);
        float4 ka = *(const float4*)(kr + d);
        acc += qa.x * ka.x + qa.y * ka.y + qa.z * ka.z + qa.w * ka.w;
    }
    float sc = acc * 0.125f;
    float mx = sc;
#pragma unroll
    for (int d = 8; d; d >>= 1) mx = fmaxf(mx, __shfl_xor_sync(0xffffffffu, mx, d));
    float p = __expf(sc - mx);
    float sm = p;
#pragma unroll
    for (int d = 8; d; d >>= 1) sm += __shfl_xor_sync(0xffffffffu, sm, d);
    at[h][g] = p / sm;
    __syncthreads();

    const int h2 = t >> 4, db = (t & 15) << 2;
    float4 o = make_float4(0.f, 0.f, 0.f, 0.f);
#pragma unroll
    for (int gg = 0; gg < 16; gg++) {
        const float w = at[h2][gg];
        const float* vr = vs + gg * 64 + db;
        o.x += w * vr[0];
        o.y += w * vr[1];
        o.z += w * vr[2];
        o.w += w * vr[3];
    }
    const size_t row = (size_t)b * 4096 + (size_t)h2 * 256 + (s >> 4);
    *(float4*)(g_x + row * 1024 + (s & 15) * 64 + db) = o;
}

// ---------------- launch ----------------
extern "C" void kernel_launch(void* const* d_in, const int* in_sizes, int n_in,
                              void* d_out, int out_size) {
    (void)in_sizes; (void)n_in; (void)out_size;
    const float* query = (const float*)d_in[0];
    const float* key   = (const float*)d_in[1];
    const float* value = (const float*)d_in[2];
    const float* Wq = (const float*)d_in[3];
    const float* bq = (const float*)d_in[4];
    const float* Wk = (const float*)d_in[5];
    const float* bk = (const float*)d_in[6];
    const float* Wv = (const float*)d_in[7];
    const float* bv = (const float*)d_in[8];
    const float* Wo = (const float*)d_in[9];
    const float* bo = (const float*)d_in[10];
    float* out = (float*)d_out;

    cudaFuncSetAttribute(qkv_mma_kernel, cudaFuncAttributeMaxDynamicSharedMemorySize, SMEM_DYN);
    cudaFuncSetAttribute(out_mma_kernel, cudaFuncAttributeMaxDynamicSharedMemorySize, SMEM_DYN);

    split_act_kernel<<<dim3(4096, 3), 256>>>(query, key, value);
    split_w_kernel<<<dim3(1024, 4), 256>>>(Wq, Wk, Wv, Wo);
    qkv_mma_kernel<<<dim3(KD / TN, MDIM / TM, 3), 256, SMEM_DYN>>>(bq, bk, bv);
    attn_kernel<<<MDIM, 256>>>();
    split_x_kernel<<<4096, 256>>>();
    out_mma_kernel<<<dim3(KD / TN, MDIM / TM, 1), 256, SMEM_DYN>>>(bo, out);
}

// round 6
// speedup vs baseline: 2.1102x; 1.0615x over previous
#include <cuda_runtime.h>
#include <cuda_bf16.h>
#include <cstdint>

// ---------------- problem constants ----------------
#define MDIM 16384          // B*S
#define KD   1024           // d_model = heads*dk
#define NELEM ((size_t)MDIM * KD)
#define WELEM ((size_t)KD * KD)

// GEMM tiling
#define TM 128
#define TN 128
#define BK 32               // k elems per chunk
#define NCH (KD / BK)       // 32 chunks
#define PITCH 40            // smem row pitch in bf16 elems (80B -> conflict-free ldmatrix)
#define TEN_BYTES (128 * PITCH * 2)        // 10240 bytes per tensor tile
#define STAGE_BYTES (4 * TEN_BYTES)        // Ah, Al, Bh, Bl
#define STAGES 3
#define SMEM_DYN (STAGES * STAGE_BYTES)    // 122880
#define NTHR 512

// ---------------- device scratch ----------------
__device__ float g_q[NELEM];
__device__ float g_k[NELEM];
__device__ float g_v[NELEM];
__device__ __nv_bfloat16 g_iqh[NELEM], g_iql[NELEM];
__device__ __nv_bfloat16 g_ikh[NELEM], g_ikl[NELEM];
__device__ __nv_bfloat16 g_ivh[NELEM], g_ivl[NELEM];
__device__ __nv_bfloat16 g_xh[NELEM],  g_xl[NELEM];
__device__ __nv_bfloat16 g_wh[4][WELEM], g_wl[4][WELEM];

// ---------------- PTX helpers ----------------
__device__ __forceinline__ uint32_t smem_u32(const void* p) {
    uint32_t a;
    asm("{ .reg .u64 t; cvta.to.shared.u64 t, %1; cvt.u32.u64 %0, t; }" : "=r"(a) : "l"(p));
    return a;
}
__device__ __forceinline__ void cp16(uint32_t dst, const void* src) {
    asm volatile("cp.async.cg.shared.global [%0], [%1], 16;" :: "r"(dst), "l"(src));
}
__device__ __forceinline__ void cp_commit() { asm volatile("cp.async.commit_group;"); }
__device__ __forceinline__ void ldm_x4(uint32_t r[4], uint32_t addr) {
    asm volatile("ldmatrix.sync.aligned.m8n8.x4.shared.b16 {%0,%1,%2,%3}, [%4];"
                 : "=r"(r[0]), "=r"(r[1]), "=r"(r[2]), "=r"(r[3]) : "r"(addr));
}
__device__ __forceinline__ void mma16816(float c[4], const uint32_t a[4],
                                         uint32_t b0, uint32_t b1) {
    asm volatile(
        "mma.sync.aligned.m16n8k16.row.col.f32.bf16.bf16.f32 "
        "{%0,%1,%2,%3}, {%4,%5,%6,%7}, {%8,%9}, {%0,%1,%2,%3};"
        : "+f"(c[0]), "+f"(c[1]), "+f"(c[2]), "+f"(c[3])
        : "r"(a[0]), "r"(a[1]), "r"(a[2]), "r"(a[3]), "r"(b0), "r"(b1));
}

// ---------------- GEMM: C[16384,1024] = A*W^T + bias (bf16x3 split) ----------------
// 512 threads, 16 warps in 4x4 grid, 32x32 warp tile, single-sync 3-buffer pipeline.
__device__ __forceinline__ void mma_gemm_body(
    const __nv_bfloat16* __restrict__ Ah, const __nv_bfloat16* __restrict__ Al,
    const __nv_bfloat16* __restrict__ Wh, const __nv_bfloat16* __restrict__ Wl,
    const float* __restrict__ bias, float* __restrict__ C)
{
    extern __shared__ char dynsm[];
    const uint32_t sb = smem_u32(dynsm);

    const int t    = threadIdx.x;
    const int lane = t & 31;
    const int wid  = t >> 5;
    const int wm   = (wid >> 2) * 32;    // warp m offset
    const int wn   = (wid & 3) * 32;     // warp n offset
    const int m0   = blockIdx.y * TM;
    const int n0   = blockIdx.x * TN;

    const char* pAh = (const char*)Ah;
    const char* pAl = (const char*)Al;
    const char* pWh = (const char*)Wh;
    const char* pWl = (const char*)Wl;

    float acc[2][4][4];
#pragma unroll
    for (int i = 0; i < 2; i++)
#pragma unroll
        for (int j = 0; j < 4; j++)
#pragma unroll
            for (int r = 0; r < 4; r++) acc[i][j][r] = 0.f;

    // per-thread load slot: 512 threads cover 128 rows x 4 (16B chunks) per tensor
    const int r0 = t >> 2, q0 = t & 3;
    const uint32_t d0 = (uint32_t)(r0 * 80 + q0 * 16);
    const size_t ga0 = (size_t)(m0 + r0) * 2048 + q0 * 16;
    const size_t gb0 = (size_t)(n0 + r0) * 2048 + q0 * 16;

    auto load_chunk = [&](int c, int buf) {
        const uint32_t s = sb + (uint32_t)buf * STAGE_BYTES;
        const size_t kb = (size_t)c * 64;
        cp16(s + d0,                 pAh + ga0 + kb);
        cp16(s + TEN_BYTES + d0,     pAl + ga0 + kb);
        cp16(s + 2 * TEN_BYTES + d0, pWh + gb0 + kb);
        cp16(s + 3 * TEN_BYTES + d0, pWl + gb0 + kb);
    };

    // prologue: 2 stages in flight (3rd buffer free for single-sync rotation)
    load_chunk(0, 0); cp_commit();
    load_chunk(1, 1); cp_commit();

    // ldmatrix lane address pieces
    const uint32_t a_row = (uint32_t)(wm + (lane & 15));
    const uint32_t a_cb  = (uint32_t)((lane >> 4) * 16);
    const uint32_t b_row = (uint32_t)(wn + (lane & 7) + ((lane >> 4) << 3));
    const uint32_t b_cb  = (uint32_t)(((lane >> 3) & 1) * 16);

#pragma unroll 1
    for (int c = 0; c < NCH; c++) {
        asm volatile("cp.async.wait_group 1;");
        __syncthreads();

        // issue next loads into the buffer consumed LAST iteration (safe post-sync)
        if (c + 2 < NCH) load_chunk(c + 2, (c + 2) % STAGES);
        cp_commit();

        const uint32_t s   = sb + (uint32_t)(c % STAGES) * STAGE_BYTES;
        const uint32_t sAh = s;
        const uint32_t sAl = s + TEN_BYTES;
        const uint32_t sBh = s + 2 * TEN_BYTES;
        const uint32_t sBl = s + 3 * TEN_BYTES;

#pragma unroll
        for (int ks = 0; ks < 2; ks++) {
            const uint32_t kb = (uint32_t)(ks * 32);
            uint32_t ah[2][4], al[2][4], bh[2][4], bl[2][4];
#pragma unroll
            for (int mt = 0; mt < 2; mt++) {
                const uint32_t ao = (a_row + mt * 16) * 80 + kb + a_cb;
                ldm_x4(ah[mt], sAh + ao);
                ldm_x4(al[mt], sAl + ao);
            }
#pragma unroll
            for (int nt = 0; nt < 2; nt++) {
                const uint32_t bo = (b_row + nt * 16) * 80 + kb + b_cb;
                ldm_x4(bh[nt], sBh + bo);
                ldm_x4(bl[nt], sBl + bo);
            }
#pragma unroll
            for (int mt = 0; mt < 2; mt++) {
#pragma unroll
                for (int j = 0; j < 4; j++) {
                    const int p = j >> 1, e = (j & 1) * 2;
                    mma16816(acc[mt][j], ah[mt], bh[p][e], bh[p][e + 1]);
                    mma16816(acc[mt][j], ah[mt], bl[p][e], bl[p][e + 1]);
                    mma16816(acc[mt][j], al[mt], bh[p][e], bh[p][e + 1]);
                }
            }
        }
    }

    // epilogue: bias + store
    const int tr = lane >> 2;
    const int tc = (lane & 3) * 2;
#pragma unroll
    for (int mt = 0; mt < 2; mt++) {
        const int gr = m0 + wm + mt * 16 + tr;
        float* row0 = C + (size_t)gr * KD + n0 + wn;
        float* row1 = row0 + 8 * KD;
#pragma unroll
        for (int j = 0; j < 4; j++) {
            const int gc = wn + j * 8 + tc;
            float2 bb = *(const float2*)(bias + n0 + gc);
            float2 o0, o1;
            o0.x = acc[mt][j][0] + bb.x;  o0.y = acc[mt][j][1] + bb.y;
            o1.x = acc[mt][j][2] + bb.x;  o1.y = acc[mt][j][3] + bb.y;
            *(float2*)(row0 + j * 8 + tc) = o0;
            *(float2*)(row1 + j * 8 + tc) = o1;
        }
    }
}

__global__ __launch_bounds__(NTHR, 1)
void qkv_mma_kernel(const float* __restrict__ bq, const float* __restrict__ bk,
                    const float* __restrict__ bv) {
    const int z = blockIdx.z;
    const __nv_bfloat16* Ah = (z == 0) ? g_iqh : (z == 1) ? g_ikh : g_ivh;
    const __nv_bfloat16* Al = (z == 0) ? g_iql : (z == 1) ? g_ikl : g_ivl;
    const float* bias = (z == 0) ? bq : (z == 1) ? bk : bv;
    float* C = (z == 0) ? g_q : (z == 1) ? g_k : g_v;
    mma_gemm_body(Ah, Al, g_wh[z], g_wl[z], bias, C);
}

__global__ __launch_bounds__(NTHR, 1)
void out_mma_kernel(const float* __restrict__ bo, float* __restrict__ out) {
    mma_gemm_body(g_xh, g_xl, g_wh[3], g_wl[3], bo, out);
}

// ---------------- fp32 -> bf16 hi/lo split ----------------
__device__ __forceinline__ void split4(const float4 v, __nv_bfloat16* hi, __nv_bfloat16* lo,
                                       size_t i4) {
    __nv_bfloat16 hx = __float2bfloat16_rn(v.x);
    __nv_bfloat16 hy = __float2bfloat16_rn(v.y);
    __nv_bfloat16 hz = __float2bfloat16_rn(v.z);
    __nv_bfloat16 hw = __float2bfloat16_rn(v.w);
    __nv_bfloat16 lx = __float2bfloat16_rn(v.x - __bfloat162float(hx));
    __nv_bfloat16 ly = __float2bfloat16_rn(v.y - __bfloat162float(hy));
    __nv_bfloat16 lz = __float2bfloat16_rn(v.z - __bfloat162float(hz));
    __nv_bfloat16 lw = __float2bfloat16_rn(v.w - __bfloat162float(hw));
    ((__nv_bfloat162*)hi)[2 * i4]     = __halves2bfloat162(hx, hy);
    ((__nv_bfloat162*)hi)[2 * i4 + 1] = __halves2bfloat162(hz, hw);
    ((__nv_bfloat162*)lo)[2 * i4]     = __halves2bfloat162(lx, ly);
    ((__nv_bfloat162*)lo)[2 * i4 + 1] = __halves2bfloat162(lz, lw);
}

__global__ __launch_bounds__(256)
void split_act_kernel(const float* __restrict__ q, const float* __restrict__ k,
                      const float* __restrict__ v) {
    const int z = blockIdx.y;
    const float* src = (z == 0) ? q : (z == 1) ? k : v;
    __nv_bfloat16* hi = (z == 0) ? g_iqh : (z == 1) ? g_ikh : g_ivh;
    __nv_bfloat16* lo = (z == 0) ? g_iql : (z == 1) ? g_ikl : g_ivl;
    const size_t n4 = NELEM / 4;
    const size_t stride = (size_t)gridDim.x * blockDim.x;
    for (size_t i = (size_t)blockIdx.x * blockDim.x + threadIdx.x; i < n4; i += stride)
        split4(((const float4*)src)[i], hi, lo, i);
}

__global__ __launch_bounds__(256)
void split_w_kernel(const float* __restrict__ wq, const float* __restrict__ wk,
                    const float* __restrict__ wv, const float* __restrict__ wo) {
    const int z = blockIdx.y;
    const float* src = (z == 0) ? wq : (z == 1) ? wk : (z == 2) ? wv : wo;
    __nv_bfloat16* hi = g_wh[z];
    __nv_bfloat16* lo = g_wl[z];
    const size_t n4 = WELEM / 4;
    const size_t stride = (size_t)gridDim.x * blockDim.x;
    for (size_t i = (size_t)blockIdx.x * blockDim.x + threadIdx.x; i < n4; i += stride)
        split4(((const float4*)src)[i], hi, lo, i);
}

// ---------------- per-token head attention, fused hi/lo output split ----------------
__global__ __launch_bounds__(256)
void attn_kernel() {
    const int token = blockIdx.x;
    const int b = token >> 12;
    const int s = token & 4095;
    __shared__ float qs[16 * 64];
    __shared__ float ks[16 * 68];
    __shared__ float vs[16 * 64];
    __shared__ float at[16][16];

    const int t = threadIdx.x;
    const size_t base = (size_t)token * 1024;
    {
        float4 qv = ((const float4*)(g_q + base))[t];
        float4 kv = ((const float4*)(g_k + base))[t];
        float4 vv = ((const float4*)(g_v + base))[t];
        ((float4*)qs)[t] = qv;
        ((float4*)vs)[t] = vv;
        const int gg = t >> 4, dd = (t & 15) << 2;
        *(float4*)(ks + gg * 68 + dd) = kv;
    }
    __syncthreads();

    const int h = t >> 4, g = t & 15;
    const float* qr = qs + h * 64;
    const float* kr = ks + g * 68;
    float acc = 0.f;
#pragma unroll
    for (int d = 0; d < 64; d += 4) {
        float4 qa = *(const float4*)(qr + d);
        float4 ka = *(const float4*)(kr + d);
        acc += qa.x * ka.x + qa.y * ka.y + qa.z * ka.z + qa.w * ka.w;
    }
    float sc = acc * 0.125f;
    float mx = sc;
#pragma unroll
    for (int d = 8; d; d >>= 1) mx = fmaxf(mx, __shfl_xor_sync(0xffffffffu, mx, d));
    float p = __expf(sc - mx);
    float sm = p;
#pragma unroll
    for (int d = 8; d; d >>= 1) sm += __shfl_xor_sync(0xffffffffu, sm, d);
    at[h][g] = p / sm;
    __syncthreads();

    const int h2 = t >> 4, db = (t & 15) << 2;
    float4 o = make_float4(0.f, 0.f, 0.f, 0.f);
#pragma unroll
    for (int gg = 0; gg < 16; gg++) {
        const float w = at[h2][gg];
        const float* vr = vs + gg * 64 + db;
        o.x += w * vr[0];
        o.y += w * vr[1];
        o.z += w * vr[2];
        o.w += w * vr[3];
    }
    // fused hi/lo bf16 split of the scrambled output
    const size_t row = (size_t)b * 4096 + (size_t)h2 * 256 + (s >> 4);
    const size_t idx = row * 1024 + (s & 15) * 64 + db;
    __nv_bfloat16 hx = __float2bfloat16_rn(o.x);
    __nv_bfloat16 hy = __float2bfloat16_rn(o.y);
    __nv_bfloat16 hz = __float2bfloat16_rn(o.z);
    __nv_bfloat16 hw = __float2bfloat16_rn(o.w);
    __nv_bfloat16 lx = __float2bfloat16_rn(o.x - __bfloat162float(hx));
    __nv_bfloat16 ly = __float2bfloat16_rn(o.y - __bfloat162float(hy));
    __nv_bfloat16 lz = __float2bfloat16_rn(o.z - __bfloat162float(hz));
    __nv_bfloat16 lw = __float2bfloat16_rn(o.w - __bfloat162float(hw));
    __nv_bfloat162 h01 = __halves2bfloat162(hx, hy), h23 = __halves2bfloat162(hz, hw);
    __nv_bfloat162 l01 = __halves2bfloat162(lx, ly), l23 = __halves2bfloat162(lz, lw);
    *(uint2*)(g_xh + idx) = make_uint2(*(uint32_t*)&h01, *(uint32_t*)&h23);
    *(uint2*)(g_xl + idx) = make_uint2(*(uint32_t*)&l01, *(uint32_t*)&l23);
}

// ---------------- launch ----------------
extern "C" void kernel_launch(void* const* d_in, const int* in_sizes, int n_in,
                              void* d_out, int out_size) {
    (void)in_sizes; (void)n_in; (void)out_size;
    const float* query = (const float*)d_in[0];
    const float* key   = (const float*)d_in[1];
    const float* value = (const float*)d_in[2];
    const float* Wq = (const float*)d_in[3];
    const float* bq = (const float*)d_in[4];
    const float* Wk = (const float*)d_in[5];
    const float* bk = (const float*)d_in[6];
    const float* Wv = (const float*)d_in[7];
    const float* bv = (const float*)d_in[8];
    const float* Wo = (const float*)d_in[9];
    const float* bo = (const float*)d_in[10];
    float* out = (float*)d_out;

    cudaFuncSetAttribute(qkv_mma_kernel, cudaFuncAttributeMaxDynamicSharedMemorySize, SMEM_DYN);
    cudaFuncSetAttribute(out_mma_kernel, cudaFuncAttributeMaxDynamicSharedMemorySize, SMEM_DYN);

    split_act_kernel<<<dim3(4096, 3), 256>>>(query, key, value);
    split_w_kernel<<<dim3(1024, 4), 256>>>(Wq, Wk, Wv, Wo);
    qkv_mma_kernel<<<dim3(KD / TN, MDIM / TM, 3), NTHR, SMEM_DYN>>>(bq, bk, bv);
    attn_kernel<<<MDIM, 256>>>();
    out_mma_kernel<<<dim3(KD / TN, MDIM / TM, 1), NTHR, SMEM_DYN>>>(bo, out);
}

// round 7
// speedup vs baseline: 2.9684x; 1.4067x over previous
#include <cuda_runtime.h>
#include <cuda_bf16.h>
#include <cstdint>

// ---------------- problem constants ----------------
#define MDIM 16384          // B*S
#define KD   1024           // d_model
#define NELEM ((size_t)MDIM * KD)
#define WELEM ((size_t)KD * KD)

// GEMM tiling: CTA 256x128, 16 warps (4x4), warp tile 64x32, BK=32 (4 k8-steps)
#define TMC 256
#define TN  128
#define BK  32
#define NCH (KD / BK)                 // 32 chunks
#define PITCHB 144                    // smem row pitch bytes (128B data + 16B pad)
#define A_BYTES (256 * PITCHB)        // 36864
#define B_BYTES (128 * PITCHB)        // 18432
#define STAGE_BYTES (A_BYTES + B_BYTES)  // 55296
#define STAGES 3
#define SMEM_DYN (STAGES * STAGE_BYTES)  // 165888
#define NTHR 512

// ---------------- device scratch ----------------
__device__ float g_aq[NELEM], g_ak[NELEM], g_av[NELEM];   // tf32-rounded activations
__device__ float g_w[4][WELEM];                            // tf32-rounded weights
__device__ float g_q[NELEM], g_k[NELEM], g_v[NELEM];       // projections
__device__ float g_x[NELEM];                               // attn out (tf32-rounded)

// ---------------- PTX helpers ----------------
__device__ __forceinline__ uint32_t smem_u32(const void* p) {
    uint32_t a;
    asm("{ .reg .u64 t; cvta.to.shared.u64 t, %1; cvt.u32.u64 %0, t; }" : "=r"(a) : "l"(p));
    return a;
}
__device__ __forceinline__ void cp16(uint32_t dst, const void* src) {
    asm volatile("cp.async.cg.shared.global [%0], [%1], 16;" :: "r"(dst), "l"(src));
}
__device__ __forceinline__ void cp_commit() { asm volatile("cp.async.commit_group;"); }
__device__ __forceinline__ void ldm_x4(uint32_t r[4], uint32_t addr) {
    asm volatile("ldmatrix.sync.aligned.m8n8.x4.shared.b16 {%0,%1,%2,%3}, [%4];"
                 : "=r"(r[0]), "=r"(r[1]), "=r"(r[2]), "=r"(r[3]) : "r"(addr));
}
__device__ __forceinline__ void mma_tf32(float c[4], const uint32_t a[4],
                                         uint32_t b0, uint32_t b1) {
    asm volatile(
        "mma.sync.aligned.m16n8k8.row.col.f32.tf32.tf32.f32 "
        "{%0,%1,%2,%3}, {%4,%5,%6,%7}, {%8,%9}, {%0,%1,%2,%3};"
        : "+f"(c[0]), "+f"(c[1]), "+f"(c[2]), "+f"(c[3])
        : "r"(a[0]), "r"(a[1]), "r"(a[2]), "r"(a[3]), "r"(b0), "r"(b1));
}
__device__ __forceinline__ float tf32r(float x) {
    uint32_t u;
    asm("cvt.rna.tf32.f32 %0, %1;" : "=r"(u) : "f"(x));
    return __uint_as_float(u);
}

// ---------------- GEMM: C[16384,1024] = A*W^T + bias (tf32 single-pass) ----------------
// A: [MDIM, KD] fp32 (tf32-rounded). W: [KD, KD] fp32 (tf32-rounded), row = out-feature.
__device__ __forceinline__ void tf32_gemm_body(
    const float* __restrict__ A, const float* __restrict__ W,
    const float* __restrict__ bias, float* __restrict__ C)
{
    extern __shared__ char dynsm[];
    const uint32_t sb = smem_u32(dynsm);

    const int t    = threadIdx.x;
    const int lane = t & 31;
    const int wid  = t >> 5;
    const int wm   = (wid >> 2) * 64;    // warp m offset (0..192)
    const int wn   = (wid & 3) * 32;     // warp n offset (0..96)
    const int m0   = blockIdx.y * TMC;
    const int n0   = blockIdx.x * TN;

    const char* pA = (const char*)A;
    const char* pW = (const char*)W;

    float acc[4][4][4];
#pragma unroll
    for (int i = 0; i < 4; i++)
#pragma unroll
        for (int j = 0; j < 4; j++)
#pragma unroll
            for (int r = 0; r < 4; r++) acc[i][j][r] = 0.f;

    // cp.async slots: A = 2048 x 16B (256 rows x 8), B = 1024 x 16B (128 rows x 8)
    // thread t covers A slots {t, t+512, t+1024, t+1536}, B slots {t, t+512}
    const int ar[4] = {t >> 3, (t + 512) >> 3, (t + 1024) >> 3, (t + 1536) >> 3};
    const int aq    = t & 7;
    const int br[2] = {t >> 3, (t + 512) >> 3};

    auto load_chunk = [&](int c, int buf) {
        const uint32_t s  = sb + (uint32_t)buf * STAGE_BYTES;
        const uint32_t sB = s + A_BYTES;
        const size_t kb = (size_t)c * 128;        // 32 floats = 128B per chunk-row
#pragma unroll
        for (int i = 0; i < 4; i++)
            cp16(s + (uint32_t)(ar[i] * PITCHB + aq * 16),
                 pA + (size_t)(m0 + ar[i]) * 4096 + kb + aq * 16);
#pragma unroll
        for (int i = 0; i < 2; i++)
            cp16(sB + (uint32_t)(br[i] * PITCHB + aq * 16),
                 pW + (size_t)(n0 + br[i]) * 4096 + kb + aq * 16);
    };

    load_chunk(0, 0); cp_commit();
    load_chunk(1, 1); cp_commit();

    // ldmatrix per-lane address pieces
    const int g  = lane >> 3;
    const int r8 = lane & 7;
    // A x4: matrices (rows 0-7,k0-3),(rows 8-15,k0-3),(rows 0-7,k4-7),(rows 8-15,k4-7)
    const uint32_t aBase = (uint32_t)((wm + (g & 1) * 8 + r8) * PITCHB + (g >> 1) * 16);
    // B x4: matrices (n0-7,k lo),(n0-7,k hi),(n8-15,k lo),(n8-15,k hi)
    const uint32_t bBase = (uint32_t)((wn + (g >> 1) * 8 + r8) * PITCHB + (g & 1) * 16);

#pragma unroll 1
    for (int c = 0; c < NCH; c++) {
        asm volatile("cp.async.wait_group 1;");
        __syncthreads();

        if (c + 2 < NCH) load_chunk(c + 2, (c + 2) % STAGES);
        cp_commit();

        const uint32_t s  = sb + (uint32_t)(c % STAGES) * STAGE_BYTES;
        const uint32_t sA = s;
        const uint32_t sB = s + A_BYTES;

#pragma unroll
        for (int ks = 0; ks < 4; ks++) {
            const uint32_t kb = (uint32_t)(ks * 32);
            uint32_t af[4][4], bf[2][4];
#pragma unroll
            for (int mt = 0; mt < 4; mt++)
                ldm_x4(af[mt], sA + aBase + (uint32_t)(mt * 16 * PITCHB) + kb);
#pragma unroll
            for (int nn = 0; nn < 2; nn++)
                ldm_x4(bf[nn], sB + bBase + (uint32_t)(nn * 16 * PITCHB) + kb);
#pragma unroll
            for (int mt = 0; mt < 4; mt++) {
#pragma unroll
                for (int j = 0; j < 4; j++) {
                    const int p = j >> 1, e = (j & 1) * 2;
                    mma_tf32(acc[mt][j], af[mt], bf[p][e], bf[p][e + 1]);
                }
            }
        }
    }

    // epilogue: bias + store
    const int tr = lane >> 2;
    const int tc = (lane & 3) * 2;
#pragma unroll
    for (int mt = 0; mt < 4; mt++) {
        const int gr = m0 + wm + mt * 16 + tr;
        float* row0 = C + (size_t)gr * KD + n0 + wn;
        float* row1 = row0 + 8 * KD;
#pragma unroll
        for (int j = 0; j < 4; j++) {
            const int gc = wn + j * 8 + tc;
            float2 bb = *(const float2*)(bias + n0 + gc);
            float2 o0, o1;
            o0.x = acc[mt][j][0] + bb.x;  o0.y = acc[mt][j][1] + bb.y;
            o1.x = acc[mt][j][2] + bb.x;  o1.y = acc[mt][j][3] + bb.y;
            *(float2*)(row0 + j * 8 + tc) = o0;
            *(float2*)(row1 + j * 8 + tc) = o1;
        }
    }
}

__global__ __launch_bounds__(NTHR, 1)
void qkv_mma_kernel(const float* __restrict__ bq, const float* __restrict__ bk,
                    const float* __restrict__ bv) {
    const int z = blockIdx.z;
    const float* A = (z == 0) ? g_aq : (z == 1) ? g_ak : g_av;
    const float* bias = (z == 0) ? bq : (z == 1) ? bk : bv;
    float* C = (z == 0) ? g_q : (z == 1) ? g_k : g_v;
    tf32_gemm_body(A, g_w[z], bias, C);
}

__global__ __launch_bounds__(NTHR, 1)
void out_mma_kernel(const float* __restrict__ bo, float* __restrict__ out) {
    tf32_gemm_body(g_x, g_w[3], bo, out);
}

// ---------------- tf32 rounding copy passes ----------------
__device__ __forceinline__ void round4(const float4 v, float* dst, size_t i4) {
    float4 o;
    o.x = tf32r(v.x); o.y = tf32r(v.y); o.z = tf32r(v.z); o.w = tf32r(v.w);
    ((float4*)dst)[i4] = o;
}

__global__ __launch_bounds__(256)
void round_act_kernel(const float* __restrict__ q, const float* __restrict__ k,
                      const float* __restrict__ v) {
    const int z = blockIdx.y;
    const float* src = (z == 0) ? q : (z == 1) ? k : v;
    float* dst = (z == 0) ? g_aq : (z == 1) ? g_ak : g_av;
    const size_t n4 = NELEM / 4;
    const size_t stride = (size_t)gridDim.x * blockDim.x;
    for (size_t i = (size_t)blockIdx.x * blockDim.x + threadIdx.x; i < n4; i += stride)
        round4(((const float4*)src)[i], dst, i);
}

__global__ __launch_bounds__(256)
void round_w_kernel(const float* __restrict__ wq, const float* __restrict__ wk,
                    const float* __restrict__ wv, const float* __restrict__ wo) {
    const int z = blockIdx.y;
    const float* src = (z == 0) ? wq : (z == 1) ? wk : (z == 2) ? wv : wo;
    float* dst = g_w[z];
    const size_t n4 = WELEM / 4;
    const size_t stride = (size_t)gridDim.x * blockDim.x;
    for (size_t i = (size_t)blockIdx.x * blockDim.x + threadIdx.x; i < n4; i += stride)
        round4(((const float4*)src)[i], dst, i);
}

// ---------------- per-token head attention, fused tf32 rounding ----------------
__global__ __launch_bounds__(256)
void attn_kernel() {
    const int token = blockIdx.x;
    const int b = token >> 12;
    const int s = token & 4095;
    __shared__ float qs[16 * 64];
    __shared__ float ks[16 * 68];
    __shared__ float vs[16 * 64];
    __shared__ float at[16][16];

    const int t = threadIdx.x;
    const size_t base = (size_t)token * 1024;
    {
        float4 qv = ((const float4*)(g_q + base))[t];
        float4 kv = ((const float4*)(g_k + base))[t];
        float4 vv = ((const float4*)(g_v + base))[t];
        ((float4*)qs)[t] = qv;
        ((float4*)vs)[t] = vv;
        const int gg = t >> 4, dd = (t & 15) << 2;
        *(float4*)(ks + gg * 68 + dd) = kv;
    }
    __syncthreads();

    const int h = t >> 4, g = t & 15;
    const float* qr = qs + h * 64;
    const float* kr = ks + g * 68;
    float acc = 0.f;
#pragma unroll
    for (int d = 0; d < 64; d += 4) {
        float4 qa = *(const float4*)(qr + d);
        float4 ka = *(const float4*)(kr + d);
        acc += qa.x * ka.x + qa.y * ka.y + qa.z * ka.z + qa.w * ka.w;
    }
    float sc = acc * 0.125f;
    float mx = sc;
#pragma unroll
    for (int d = 8; d; d >>= 1) mx = fmaxf(mx, __shfl_xor_sync(0xffffffffu, mx, d));
    float p = __expf(sc - mx);
    float sm = p;
#pragma unroll
    for (int d = 8; d; d >>= 1) sm += __shfl_xor_sync(0xffffffffu, sm, d);
    at[h][g] = p / sm;
    __syncthreads();

    const int h2 = t >> 4, db = (t & 15) << 2;
    float4 o = make_float4(0.f, 0.f, 0.f, 0.f);
#pragma unroll
    for (int gg = 0; gg < 16; gg++) {
        const float w = at[h2][gg];
        const float* vr = vs + gg * 64 + db;
        o.x += w * vr[0];
        o.y += w * vr[1];
        o.z += w * vr[2];
        o.w += w * vr[3];
    }
    // scrambled layout + tf32 rounding (feeds the tf32 out-GEMM directly)
    const size_t row = (size_t)b * 4096 + (size_t)h2 * 256 + (s >> 4);
    const size_t idx = row * 1024 + (s & 15) * 64 + db;
    float4 ro;
    ro.x = tf32r(o.x); ro.y = tf32r(o.y); ro.z = tf32r(o.z); ro.w = tf32r(o.w);
    *(float4*)(g_x + idx) = ro;
}

// ---------------- launch ----------------
extern "C" void kernel_launch(void* const* d_in, const int* in_sizes, int n_in,
                              void* d_out, int out_size) {
    (void)in_sizes; (void)n_in; (void)out_size;
    const float* query = (const float*)d_in[0];
    const float* key   = (const float*)d_in[1];
    const float* value = (const float*)d_in[2];
    const float* Wq = (const float*)d_in[3];
    const float* bq = (const float*)d_in[4];
    const float* Wk = (const float*)d_in[5];
    const float* bk = (const float*)d_in[6];
    const float* Wv = (const float*)d_in[7];
    const float* bv = (const float*)d_in[8];
    const float* Wo = (const float*)d_in[9];
    const float* bo = (const float*)d_in[10];
    float* out = (float*)d_out;

    cudaFuncSetAttribute(qkv_mma_kernel, cudaFuncAttributeMaxDynamicSharedMemorySize, SMEM_DYN);
    cudaFuncSetAttribute(out_mma_kernel, cudaFuncAttributeMaxDynamicSharedMemorySize, SMEM_DYN);

    round_act_kernel<<<dim3(4096, 3), 256>>>(query, key, value);
    round_w_kernel<<<dim3(1024, 4), 256>>>(Wq, Wk, Wv, Wo);
    qkv_mma_kernel<<<dim3(KD / TN, MDIM / TMC, 3), NTHR, SMEM_DYN>>>(bq, bk, bv);
    attn_kernel<<<MDIM, 256>>>();
    out_mma_kernel<<<dim3(KD / TN, MDIM / TMC, 1), NTHR, SMEM_DYN>>>(bo, out);
}